// round 7
// baseline (speedup 1.0000x reference)
#include <cuda_runtime.h>
#include <cuda_bf16.h>
#include <math.h>
#include <math_constants.h>
#include <stdint.h>

// Problem constants (fixed by setup_inputs)
#define BQ 2
#define LQ 256
#define HQ 256
#define CQ 5
#define VOCAB 255      // 2*127+1 distinct clipped distances
#define D4H 1024       // 4*H

// Scratch (device globals — no allocations allowed)
__device__ __align__(16) float g_T[VOCAB * HQ];          // sin-table @ Wh_w [255,256]
__device__ __align__(16) float g_A[BQ * LQ * HQ];        // hs@(We+Wd)+b    [B,L,H]
__device__ __align__(16) float g_Bv[BQ * LQ * HQ];       // hs@(Ws-Wd)      [B,L,H]
__device__ __align__(16) __nv_bfloat16 g_WmT[HQ * HQ];   // Wm^T bf16 [h][k]

// ---------------------------------------------------------------------------
// helpers
// ---------------------------------------------------------------------------
__device__ __forceinline__ uint32_t smem_u32(const void* p) {
    uint32_t a;
    asm("{ .reg .u64 t; cvta.to.shared.u64 t, %1; cvt.u32.u64 %0, t; }"
        : "=r"(a) : "l"(p));
    return a;
}
__device__ __forceinline__ float tanhfast(float x) {
    float r;
    asm("tanh.approx.f32 %0, %1;" : "=f"(r) : "f"(x));
    return r;
}
#define LDSM4(R0, R1, R2, R3, ADDR) \
    asm volatile("ldmatrix.sync.aligned.m8n8.x4.shared.b16 {%0,%1,%2,%3}, [%4];" \
                 : "=r"(R0), "=r"(R1), "=r"(R2), "=r"(R3) : "r"(ADDR))
#define MMA16816(D, A, B) \
    asm volatile("mma.sync.aligned.m16n8k16.row.col.f32.bf16.bf16.f32 " \
                 "{%0,%1,%2,%3},{%4,%5,%6,%7},{%8,%9},{%0,%1,%2,%3};" \
                 : "+f"((D)[0]), "+f"((D)[1]), "+f"((D)[2]), "+f"((D)[3]) \
                 : "r"((A)[0]), "r"((A)[1]), "r"((A)[2]), "r"((A)[3]), \
                   "r"((B)[0]), "r"((B)[1]))
#define CP_ASYNC16(dst, src) \
    asm volatile("cp.async.cg.shared.global [%0], [%1], 16;" :: "r"(dst), "l"(src))
#define CP_COMMIT() asm volatile("cp.async.commit_group;" ::: "memory")
#define CP_WAIT0()  asm volatile("cp.async.wait_group 0;" ::: "memory")

// ---------------------------------------------------------------------------
// Kernel: T[p,:] = sinusoid_row(p) @ Wh_w.  64 blocks x 256 thr, 4 rows/block
// (amortizes the 1 MB Wh_w stream 4x). Sinusoid matches numpy exactly enough:
// div = 10000^((2*(i//2))/1024); even->sin, odd->cos.
// ---------------------------------------------------------------------------
__global__ void k_tgemm(const float* __restrict__ Wh_w) {
    __shared__ float s[4][D4H];
    const int p0 = blockIdx.x * 4;
    const int t = threadIdx.x;
    for (int idx = t; idx < 4 * D4H; idx += 256) {
        int r = idx >> 10, i = idx & 1023;
        int p = p0 + r;
        float v = 0.f;
        if (p < VOCAB) {
            float e = (float)(2 * (i >> 1)) * (13.287712379549449f / 1024.f);
            float ang = (float)p * exp2f(-e);
            v = (i & 1) ? cosf(ang) : sinf(ang);
        }
        s[r][i] = v;
    }
    __syncthreads();
    float a0 = 0.f, a1 = 0.f, a2 = 0.f, a3 = 0.f;
    #pragma unroll 8
    for (int k = 0; k < D4H; ++k) {
        float w = Wh_w[k * HQ + t];
        a0 = fmaf(s[0][k], w, a0);
        a1 = fmaf(s[1][k], w, a1);
        a2 = fmaf(s[2][k], w, a2);
        a3 = fmaf(s[3][k], w, a3);
    }
    if (p0     < VOCAB) g_T[(p0    ) * HQ + t] = a0;
    if (p0 + 1 < VOCAB) g_T[(p0 + 1) * HQ + t] = a1;
    if (p0 + 2 < VOCAB) g_T[(p0 + 2) * HQ + t] = a2;
    if (p0 + 3 < VOCAB) g_T[(p0 + 3) * HQ + t] = a3;
}

// ---------------------------------------------------------------------------
// Kernel: A = hs@(We+Wd)+Wh_b, Bv = hs@(Ws-Wd)
// ---------------------------------------------------------------------------
__global__ void k_ab(const float* __restrict__ hs,
                     const float* __restrict__ Wh_w,
                     const float* __restrict__ Wh_b) {
    __shared__ float s_hs[8][HQ];
    const int blk = blockIdx.x;
    const int b = blk >> 5;
    const int i0 = (blk & 31) * 8;
    const int t = threadIdx.x;
    #pragma unroll
    for (int n = 0; n < 8; ++n) {
        int idx = t + n * 256;
        s_hs[idx >> 8][idx & 255] = hs[(b * LQ + i0 + (idx >> 8)) * HQ + (idx & 255)];
    }
    __syncthreads();
    float accA[8] = {0,0,0,0,0,0,0,0};
    float accB[8] = {0,0,0,0,0,0,0,0};
    const int h = t;
    #pragma unroll 4
    for (int k = 0; k < HQ; ++k) {
        float we = Wh_w[k * HQ + h];
        float ws = Wh_w[(HQ + k) * HQ + h];
        float wd = Wh_w[(2 * HQ + k) * HQ + h];
        float wa = we + wd, wb = ws - wd;
        #pragma unroll
        for (int r = 0; r < 8; ++r) {
            float x = s_hs[r][k];
            accA[r] = fmaf(x, wa, accA[r]);
            accB[r] = fmaf(x, wb, accB[r]);
        }
    }
    float bias = Wh_b[h];
    #pragma unroll
    for (int r = 0; r < 8; ++r) {
        g_A[(b * LQ + i0 + r) * HQ + h]  = accA[r] + bias;
        g_Bv[(b * LQ + i0 + r) * HQ + h] = accB[r];
    }
}

// ---------------------------------------------------------------------------
// Kernel: WmT[h][k] = bf16(Wm[k][h]),  Wm = Wh_w rows [768,1024)
// ---------------------------------------------------------------------------
__global__ void k_trans(const float* __restrict__ Wh_w) {
    __shared__ float tile[32][33];
    const int k0 = blockIdx.x * 32, h0 = blockIdx.y * 32;
    const int tx = threadIdx.x, ty = threadIdx.y;
    tile[ty][tx] = Wh_w[(3 * HQ + k0 + ty) * HQ + h0 + tx];
    __syncthreads();
    g_WmT[(h0 + ty) * HQ + k0 + tx] = __float2bfloat16(tile[tx][ty]);
}

// ---------------------------------------------------------------------------
// Main fused kernel (mma.sync bf16, double-buffered, cp.async B prefetch):
// block (b, i, j-tile of 128): D[j,h] = sum_k (hs_j[k]*hs_i[k]) * Wm[k,h]
// 512 threads = 16 warps in 4(j) x 4(h); warp tile 32j x 64h.
// Pipeline: while MMA runs on buf[c&1], LDG for A(c+1) and cp.async for
// B(c+1) are in flight into buf[(c+1)&1]; one __syncthreads per chunk.
// Epilogue: pre = D + A_i + Bv_j + T[clip(j-i)]; tanh; @Wo; reduce; mask.
// ---------------------------------------------------------------------------
#define RS 40            // smem row stride in bf16 (80 B) -> conflict-free ldmatrix
#define SA0   0          // A buf0: 128*RS*2 = 10240 B
#define SA1   10240      // A buf1
#define SB0   20480      // B buf0: 256*RS*2 = 20480 B
#define SB1   40960      // B buf1
#define SHI   61440      // 256 f32
#define SAI   62464      // 256 f32
#define SWOT  63488      // 5*256 f32
#define SPART 68608      // 5*128 f32
#define SMTOT 71168

__global__ void __launch_bounds__(512, 1)
k_main(const float* __restrict__ hs,
       const int*   __restrict__ mask,
       const float* __restrict__ Wo_w,
       const float* __restrict__ Wo_b,
       float* __restrict__ out) {
    extern __shared__ char dsm[];
    const uint32_t sbase = smem_u32(dsm);
    float* sHi   = (float*)(dsm + SHI);
    float* sAi   = (float*)(dsm + SAI);
    float* sWoT  = (float*)(dsm + SWOT);    // [c][h] = c*HQ + h
    float* sPart = (float*)(dsm + SPART);   // [c][j] = c*128 + j

    const int t = threadIdx.x;
    const int lane = t & 31, w = t >> 5;
    const int warp_j = w >> 2, warp_h = w & 3;
    const int j0 = blockIdx.x * 128;
    const int i_g = blockIdx.y;
    const int b = blockIdx.z;

    const int jrow_f = t >> 2;             // A fill: row 0..127
    const int k0_f   = (t & 3) * 8;        // A fill: k-group base
    const float* hsrowj = hs + (b * LQ + j0 + jrow_f) * HQ;

    const int brow_f = t >> 2;             // B fill rows: idx>>2 for it*512+t
    // (B fill addresses computed inline)

    // -- start chunk-0 prefetch immediately (doesn't need smem) --
    float4 lo = *(const float4*)(hsrowj + k0_f);
    float4 hi = *(const float4*)(hsrowj + k0_f + 4);
    #pragma unroll
    for (int it = 0; it < 2; ++it) {
        int idx = it * 512 + t;
        int row = idx >> 2, kg = (idx & 3) * 8;
        CP_ASYNC16(sbase + SB0 + row * (RS * 2) + kg * 2,
                   g_WmT + row * HQ + kg);
    }
    CP_COMMIT();

    // -- prefill small smem arrays --
    if (t < HQ) {
        sHi[t] = hs[(b * LQ + i_g) * HQ + t];
        sAi[t] = g_A[(b * LQ + i_g) * HQ + t];
    }
    for (int idx = t; idx < HQ * CQ; idx += 512) {
        int h = idx / CQ, c = idx % CQ;
        sWoT[c * HQ + h] = Wo_w[idx];
    }
    for (int idx = t; idx < CQ * 128; idx += 512) sPart[idx] = 0.f;
    __syncthreads();                        // sHi ready for A convert

    // -- convert + store chunk-0 A tile --
    {
        const float* hv = &sHi[k0_f];
        __nv_bfloat162 p0 = __floats2bfloat162_rn(lo.x * hv[0], lo.y * hv[1]);
        __nv_bfloat162 p1 = __floats2bfloat162_rn(lo.z * hv[2], lo.w * hv[3]);
        __nv_bfloat162 p2 = __floats2bfloat162_rn(hi.x * hv[4], hi.y * hv[5]);
        __nv_bfloat162 p3 = __floats2bfloat162_rn(hi.z * hv[6], hi.w * hv[7]);
        uint4 v;
        v.x = *(uint32_t*)&p0; v.y = *(uint32_t*)&p1;
        v.z = *(uint32_t*)&p2; v.w = *(uint32_t*)&p3;
        *(uint4*)(dsm + SA0 + jrow_f * (RS * 2) + k0_f * 2) = v;
    }
    CP_WAIT0();
    __syncthreads();                        // buf0 complete

    float acc[2][8][4];
    #pragma unroll
    for (int jt = 0; jt < 2; ++jt)
        #pragma unroll
        for (int ht = 0; ht < 8; ++ht)
            #pragma unroll
            for (int u = 0; u < 4; ++u) acc[jt][ht][u] = 0.f;

    #pragma unroll 1
    for (int c = 0; c < 8; ++c) {
        const int cb = c & 1;
        const uint32_t aOff = cb ? SA1 : SA0;
        const uint32_t bOff = cb ? SB1 : SB0;
        const uint32_t aOffN = cb ? SA0 : SA1;
        const uint32_t bOffN = cb ? SB0 : SB1;

        // ---- prefetch chunk c+1 (in flight during MMA) ----
        if (c < 7) {
            const int kcn = (c + 1) * 32;
            lo = *(const float4*)(hsrowj + kcn + k0_f);
            hi = *(const float4*)(hsrowj + kcn + k0_f + 4);
            #pragma unroll
            for (int it = 0; it < 2; ++it) {
                int idx = it * 512 + t;
                int row = idx >> 2, kg = (idx & 3) * 8;
                CP_ASYNC16(sbase + bOffN + row * (RS * 2) + kg * 2,
                           g_WmT + row * HQ + kcn + kg);
            }
            CP_COMMIT();
        }

        // ---- MMA on current buffers ----
        #pragma unroll
        for (int kk = 0; kk < 32; kk += 16) {
            uint32_t aF[2][4];
            #pragma unroll
            for (int jt = 0; jt < 2; ++jt) {
                int row = warp_j * 32 + jt * 16 + (lane & 15);
                int ko = kk + ((lane >> 4) << 3);
                LDSM4(aF[jt][0], aF[jt][1], aF[jt][2], aF[jt][3],
                      sbase + aOff + row * (RS * 2) + ko * 2);
            }
            #pragma unroll
            for (int p = 0; p < 4; ++p) {
                uint32_t b0, b1, b2, b3;
                int row = warp_h * 64 + p * 16 + (lane & 7) + ((lane >> 4) << 3);
                int ko = kk + (((lane >> 3) & 1) << 3);
                LDSM4(b0, b1, b2, b3, sbase + bOff + row * (RS * 2) + ko * 2);
                uint32_t bp0[2] = {b0, b1}, bp1[2] = {b2, b3};
                #pragma unroll
                for (int jt = 0; jt < 2; ++jt) {
                    MMA16816(acc[jt][2 * p],     aF[jt], bp0);
                    MMA16816(acc[jt][2 * p + 1], aF[jt], bp1);
                }
            }
        }

        // ---- finish chunk c+1 A tile into the other buffer ----
        if (c < 7) {
            const int kcn = (c + 1) * 32;
            const float* hv = &sHi[kcn + k0_f];
            __nv_bfloat162 p0 = __floats2bfloat162_rn(lo.x * hv[0], lo.y * hv[1]);
            __nv_bfloat162 p1 = __floats2bfloat162_rn(lo.z * hv[2], lo.w * hv[3]);
            __nv_bfloat162 p2 = __floats2bfloat162_rn(hi.x * hv[4], hi.y * hv[5]);
            __nv_bfloat162 p3 = __floats2bfloat162_rn(hi.z * hv[6], hi.w * hv[7]);
            uint4 v;
            v.x = *(uint32_t*)&p0; v.y = *(uint32_t*)&p1;
            v.z = *(uint32_t*)&p2; v.w = *(uint32_t*)&p3;
            *(uint4*)(dsm + aOffN + jrow_f * (RS * 2) + k0_f * 2) = v;
        }
        CP_WAIT0();
        __syncthreads();
    }

    // ---- epilogue ----
    const int g  = lane >> 2;
    const int c2 = (lane & 3) << 1;

    #pragma unroll
    for (int jt = 0; jt < 2; ++jt) {
        #pragma unroll
        for (int rr = 0; rr < 2; ++rr) {
            const int j_loc = warp_j * 32 + jt * 16 + rr * 8 + g;
            const int j_g = j0 + j_loc;
            int d = j_g - i_g;
            d = (d > 127 ? 127 : (d < -127 ? -127 : d)) + 127;
            const float* rB = g_Bv + (b * LQ + j_g) * HQ;
            const float* rT = g_T + d * HQ;
            float part[5] = {0.f, 0.f, 0.f, 0.f, 0.f};
            #pragma unroll
            for (int ht = 0; ht < 8; ++ht) {
                const int h = warp_h * 64 + ht * 8 + c2;
                float dv0 = acc[jt][ht][rr * 2 + 0];
                float dv1 = acc[jt][ht][rr * 2 + 1];
                float2 bv = *(const float2*)(rB + h);
                float2 tv = *(const float2*)(rT + h);
                float th0 = tanhfast(dv0 + sAi[h]     + bv.x + tv.x);
                float th1 = tanhfast(dv1 + sAi[h + 1] + bv.y + tv.y);
                #pragma unroll
                for (int cc = 0; cc < 5; ++cc) {
                    float2 wv = *(const float2*)&sWoT[cc * HQ + h];
                    part[cc] = fmaf(th0, wv.x, fmaf(th1, wv.y, part[cc]));
                }
            }
            #pragma unroll
            for (int cc = 0; cc < 5; ++cc) {
                part[cc] += __shfl_xor_sync(0xffffffffu, part[cc], 1);
                part[cc] += __shfl_xor_sync(0xffffffffu, part[cc], 2);
            }
            if ((lane & 3) == 0) {
                #pragma unroll
                for (int cc = 0; cc < 5; ++cc)
                    atomicAdd(&sPart[cc * 128 + j_loc], part[cc]);
            }
        }
    }
    __syncthreads();

    const int mi = mask[b * LQ + i_g];
    for (int idx = t; idx < CQ * 128; idx += 512) {
        const int cc = idx >> 7, jl = idx & 127;
        const int j_g = j0 + jl;
        const int mj = mask[b * LQ + j_g];
        float v = sPart[cc * 128 + jl] + Wo_b[cc];
        if (mi == 0 || mj == 0) v = -CUDART_INF_F;
        else if (i_g > j_g)     v -= 1e12f;
        out[((b * CQ + cc) * LQ + i_g) * LQ + j_g] = v;
    }
}

// ---------------------------------------------------------------------------
extern "C" void kernel_launch(void* const* d_in, const int* in_sizes, int n_in,
                              void* d_out, int out_size) {
    const float* hs   = nullptr;   // 131072
    const int*   mask = nullptr;   // 512
    const float* Wh_w = nullptr;   // 262144
    const float* Wh_b = nullptr;   // 256
    const float* Wo_w = nullptr;   // 1280
    const float* Wo_b = nullptr;   // 5
    for (int i = 0; i < n_in; ++i) {
        switch (in_sizes[i]) {
            case 131072: hs   = (const float*)d_in[i]; break;
            case 512:    mask = (const int*)  d_in[i]; break;
            case 262144: Wh_w = (const float*)d_in[i]; break;
            case 256:    Wh_b = (const float*)d_in[i]; break;
            case 1280:   Wo_w = (const float*)d_in[i]; break;
            case 5:      Wo_b = (const float*)d_in[i]; break;
        }
    }
    float* out = (float*)d_out;

    cudaFuncSetAttribute(k_main, cudaFuncAttributeMaxDynamicSharedMemorySize, SMTOT);

    k_tgemm<<<64, 256>>>(Wh_w);
    k_ab<<<64, 256>>>(hs, Wh_w, Wh_b);
    {
        dim3 g(8, 8); dim3 blk(32, 32);
        k_trans<<<g, blk>>>(Wh_w);
    }
    {
        dim3 grid(LQ / 128, LQ, BQ);     // (2, 256, 2) = 1024 blocks
        k_main<<<grid, 512, SMTOT>>>(hs, mask, Wo_w, Wo_b, out);
    }
}

// round 8
// speedup vs baseline: 2.3403x; 2.3403x over previous
#include <cuda_runtime.h>
#include <cuda_bf16.h>
#include <math.h>
#include <math_constants.h>
#include <stdint.h>

// Problem constants (fixed by setup_inputs)
#define BQ 2
#define LQ 256
#define HQ 256
#define CQ 5
#define VOCAB 255      // 2*127+1 distinct clipped distances
#define D4H 1024       // 4*H

// Scratch (device globals — no allocations allowed)
__device__ __align__(16) float g_T[VOCAB * HQ];          // sin-table @ Wh_w [255,256]
__device__ __align__(16) float g_A[BQ * LQ * HQ];        // hs@(We+Wd)+b    [B,L,H]
__device__ __align__(16) float g_Bv[BQ * LQ * HQ];       // hs@(Ws-Wd)      [B,L,H]
__device__ __align__(16) __nv_bfloat16 g_WmT[HQ * HQ];   // Wm^T bf16 [h][k]

// ---------------------------------------------------------------------------
// helpers
// ---------------------------------------------------------------------------
__device__ __forceinline__ uint32_t smem_u32(const void* p) {
    uint32_t a;
    asm("{ .reg .u64 t; cvta.to.shared.u64 t, %1; cvt.u32.u64 %0, t; }"
        : "=r"(a) : "l"(p));
    return a;
}
__device__ __forceinline__ float tanhfast(float x) {
    float r;
    asm("tanh.approx.f32 %0, %1;" : "=f"(r) : "f"(x));
    return r;
}
#define LDSM4(R0, R1, R2, R3, ADDR) \
    asm volatile("ldmatrix.sync.aligned.m8n8.x4.shared.b16 {%0,%1,%2,%3}, [%4];" \
                 : "=r"(R0), "=r"(R1), "=r"(R2), "=r"(R3) : "r"(ADDR))
#define MMA16816(D, A, B) \
    asm volatile("mma.sync.aligned.m16n8k16.row.col.f32.bf16.bf16.f32 " \
                 "{%0,%1,%2,%3},{%4,%5,%6,%7},{%8,%9},{%0,%1,%2,%3};" \
                 : "+f"((D)[0]), "+f"((D)[1]), "+f"((D)[2]), "+f"((D)[3]) \
                 : "r"((A)[0]), "r"((A)[1]), "r"((A)[2]), "r"((A)[3]), \
                   "r"((B)[0]), "r"((B)[1]))

// ---------------------------------------------------------------------------
// Fused prep kernel: 192 blocks x 256 threads.
//   blocks [0,64):    T[p,:] = sinusoid_row(p) @ Wh_w, 4 rows per block
//   blocks [64,128):  A = hs@(We+Wd)+Wh_b, Bv = hs@(Ws-Wd)
//   blocks [128,192): WmT[h][k] = bf16(Wm[k][h])
// Running all three concurrently fills the chip (each alone is 64 blocks).
// ---------------------------------------------------------------------------
__global__ void __launch_bounds__(256)
k_prep(const float* __restrict__ hs,
       const float* __restrict__ Wh_w,
       const float* __restrict__ Wh_b) {
    __shared__ float smem[4 * D4H];     // 16 KB, reused per branch
    const int bx = blockIdx.x;
    const int t = threadIdx.x;

    if (bx < 64) {
        // ---- sinusoid-table GEMM: rows p0..p0+3 ----
        float (*s)[D4H] = (float(*)[D4H])smem;
        const int p0 = bx * 4;
        for (int idx = t; idx < 4 * D4H; idx += 256) {
            int r = idx >> 10, i = idx & 1023;
            int p = p0 + r;
            float v = 0.f;
            if (p < VOCAB) {
                float e = (float)(2 * (i >> 1)) * (13.287712379549449f / 1024.f);
                float ang = (float)p * exp2f(-e);
                v = (i & 1) ? cosf(ang) : sinf(ang);
            }
            s[r][i] = v;
        }
        __syncthreads();
        float a0 = 0.f, a1 = 0.f, a2 = 0.f, a3 = 0.f;
        #pragma unroll 8
        for (int k = 0; k < D4H; ++k) {
            float wv = Wh_w[k * HQ + t];
            a0 = fmaf(s[0][k], wv, a0);
            a1 = fmaf(s[1][k], wv, a1);
            a2 = fmaf(s[2][k], wv, a2);
            a3 = fmaf(s[3][k], wv, a3);
        }
        if (p0     < VOCAB) g_T[(p0    ) * HQ + t] = a0;
        if (p0 + 1 < VOCAB) g_T[(p0 + 1) * HQ + t] = a1;
        if (p0 + 2 < VOCAB) g_T[(p0 + 2) * HQ + t] = a2;
        if (p0 + 3 < VOCAB) g_T[(p0 + 3) * HQ + t] = a3;
    } else if (bx < 128) {
        // ---- A / Bv GEMMs ----
        float (*s_hs)[HQ] = (float(*)[HQ])smem;
        const int blk = bx - 64;
        const int b = blk >> 5;
        const int i0 = (blk & 31) * 8;
        #pragma unroll
        for (int n = 0; n < 8; ++n) {
            int idx = t + n * 256;
            s_hs[idx >> 8][idx & 255] = hs[(b * LQ + i0 + (idx >> 8)) * HQ + (idx & 255)];
        }
        __syncthreads();
        float accA[8] = {0,0,0,0,0,0,0,0};
        float accB[8] = {0,0,0,0,0,0,0,0};
        const int h = t;
        #pragma unroll 4
        for (int k = 0; k < HQ; ++k) {
            float we = Wh_w[k * HQ + h];
            float ws = Wh_w[(HQ + k) * HQ + h];
            float wd = Wh_w[(2 * HQ + k) * HQ + h];
            float wa = we + wd, wb = ws - wd;
            #pragma unroll
            for (int r = 0; r < 8; ++r) {
                float x = s_hs[r][k];
                accA[r] = fmaf(x, wa, accA[r]);
                accB[r] = fmaf(x, wb, accB[r]);
            }
        }
        float bias = Wh_b[h];
        #pragma unroll
        for (int r = 0; r < 8; ++r) {
            g_A[(b * LQ + i0 + r) * HQ + h]  = accA[r] + bias;
            g_Bv[(b * LQ + i0 + r) * HQ + h] = accB[r];
        }
    } else {
        // ---- WmT transpose to bf16 ----
        float (*tile)[33] = (float(*)[33])smem;   // 32x33
        const int blk = bx - 128;
        const int k0 = (blk & 7) * 32, h0 = (blk >> 3) * 32;
        const int r8 = t >> 5, c32 = t & 31;
        #pragma unroll
        for (int p = 0; p < 4; ++p) {
            int kk = p * 8 + r8;
            tile[kk][c32] = Wh_w[(3 * HQ + k0 + kk) * HQ + h0 + c32];
        }
        __syncthreads();
        #pragma unroll
        for (int p = 0; p < 4; ++p) {
            int hh = p * 8 + r8;
            g_WmT[(h0 + hh) * HQ + k0 + c32] = __float2bfloat16(tile[c32][hh]);
        }
    }
}

// ---------------------------------------------------------------------------
// Main fused kernel (mma.sync bf16, register-prefetch pipeline, plain LDG so
// WmT stays L1-resident):
// block (b, i, j-tile of 128): D[j,h] = sum_k (hs_j[k]*hs_i[k]) * Wm[k,h]
// 512 threads = 16 warps in 4(j) x 4(h); warp tile 32j x 64h.
// Per chunk: STS(prefetched regs) -> sync -> LDG(next chunk) -> MMA -> sync.
// Epilogue: pre = D + A_i + Bv_j + T[clip(j-i)]; tanh; @Wo; per-warp_h
// partial slices in smem (no atomics); final sum + mask/tril write.
// ---------------------------------------------------------------------------
#define RS 40   // smem row stride in bf16 (80 B) -> conflict-free ldmatrix

__global__ void __launch_bounds__(512, 1)
k_main(const float* __restrict__ hs,
       const int*   __restrict__ mask,
       const float* __restrict__ Wo_w,
       const float* __restrict__ Wo_b,
       float* __restrict__ out) {
    __shared__ __align__(16) __nv_bfloat16 sA[128 * RS];   // 10 KB
    __shared__ __align__(16) __nv_bfloat16 sB[256 * RS];   // 20 KB
    __shared__ float sHi[HQ];
    __shared__ float sAi[HQ];
    __shared__ float sWoT[CQ][HQ];                          // 5 KB
    __shared__ float sPart[4][CQ][128];                     // 10 KB, per-warp_h

    const int t = threadIdx.x;
    const int lane = t & 31, w = t >> 5;
    const int warp_j = w >> 2, warp_h = w & 3;
    const int j0 = blockIdx.x * 128;
    const int i_g = blockIdx.y;
    const int b = blockIdx.z;

    const int jrow_f = t >> 2;             // A fill: row 0..127
    const int k0_f   = (t & 3) * 8;        // A fill: k-group base
    const float* hsrowj = hs + (b * LQ + j0 + jrow_f) * HQ;
    const int brow0 = t >> 2;              // B fill row (it=0)
    const int brow1 = 128 + (t >> 2);      // B fill row (it=1)
    const int bkg   = (t & 3) * 8;

    // ---- prefetch chunk 0 into registers ----
    float4 lo = *(const float4*)(hsrowj + k0_f);
    float4 hi = *(const float4*)(hsrowj + k0_f + 4);
    uint4 bv0 = *(const uint4*)(g_WmT + brow0 * HQ + bkg);
    uint4 bv1 = *(const uint4*)(g_WmT + brow1 * HQ + bkg);

    // ---- prefill small smem arrays ----
    if (t < HQ) {
        sHi[t] = hs[(b * LQ + i_g) * HQ + t];
        sAi[t] = g_A[(b * LQ + i_g) * HQ + t];
    }
    for (int idx = t; idx < HQ * CQ; idx += 512) {
        int h = idx / CQ, c = idx % CQ;
        sWoT[c][h] = Wo_w[idx];
    }
    __syncthreads();                        // sHi ready

    const uint32_t sAb = smem_u32(sA);
    const uint32_t sBb = smem_u32(sB);

    float acc[2][8][4];
    #pragma unroll
    for (int jt = 0; jt < 2; ++jt)
        #pragma unroll
        for (int ht = 0; ht < 8; ++ht)
            #pragma unroll
            for (int u = 0; u < 4; ++u) acc[jt][ht][u] = 0.f;

    #pragma unroll 1
    for (int c = 0; c < 8; ++c) {
        // ---- STS current chunk from registers ----
        {
            const float* hv = &sHi[c * 32 + k0_f];
            __nv_bfloat162 p0 = __floats2bfloat162_rn(lo.x * hv[0], lo.y * hv[1]);
            __nv_bfloat162 p1 = __floats2bfloat162_rn(lo.z * hv[2], lo.w * hv[3]);
            __nv_bfloat162 p2 = __floats2bfloat162_rn(hi.x * hv[4], hi.y * hv[5]);
            __nv_bfloat162 p3 = __floats2bfloat162_rn(hi.z * hv[6], hi.w * hv[7]);
            uint4 v;
            v.x = *(uint32_t*)&p0; v.y = *(uint32_t*)&p1;
            v.z = *(uint32_t*)&p2; v.w = *(uint32_t*)&p3;
            *(uint4*)((char*)sA + jrow_f * (RS * 2) + k0_f * 2) = v;
            *(uint4*)((char*)sB + brow0 * (RS * 2) + bkg * 2) = bv0;
            *(uint4*)((char*)sB + brow1 * (RS * 2) + bkg * 2) = bv1;
        }
        __syncthreads();

        // ---- issue next chunk's LDGs (hidden behind MMA) ----
        if (c < 7) {
            const int kcn = (c + 1) * 32;
            lo  = *(const float4*)(hsrowj + kcn + k0_f);
            hi  = *(const float4*)(hsrowj + kcn + k0_f + 4);
            bv0 = *(const uint4*)(g_WmT + brow0 * HQ + kcn + bkg);
            bv1 = *(const uint4*)(g_WmT + brow1 * HQ + kcn + bkg);
        }

        // ---- MMA: 2 k-steps of 16 (R6 ordering: all fragments up front) ----
        #pragma unroll
        for (int kk = 0; kk < 32; kk += 16) {
            uint32_t aF[2][4];
            #pragma unroll
            for (int jt = 0; jt < 2; ++jt) {
                int row = warp_j * 32 + jt * 16 + (lane & 15);
                int ko = kk + ((lane >> 4) << 3);
                LDSM4(aF[jt][0], aF[jt][1], aF[jt][2], aF[jt][3],
                      sAb + row * (RS * 2) + ko * 2);
            }
            uint32_t bF[8][2];
            #pragma unroll
            for (int p = 0; p < 4; ++p) {
                int row = warp_h * 64 + p * 16 + (lane & 7) + ((lane >> 4) << 3);
                int ko = kk + (((lane >> 3) & 1) << 3);
                LDSM4(bF[2 * p][0], bF[2 * p][1], bF[2 * p + 1][0], bF[2 * p + 1][1],
                      sBb + row * (RS * 2) + ko * 2);
            }
            #pragma unroll
            for (int jt = 0; jt < 2; ++jt)
                #pragma unroll
                for (int ht = 0; ht < 8; ++ht)
                    MMA16816(acc[jt][ht], aF[jt], bF[ht]);
        }
        __syncthreads();      // protect smem before next STS
    }

    // ---- epilogue (atomic-free: per-warp_h partial slices) ----
    const int g  = lane >> 2;
    const int c2 = (lane & 3) << 1;

    #pragma unroll
    for (int jt = 0; jt < 2; ++jt) {
        #pragma unroll
        for (int rr = 0; rr < 2; ++rr) {
            const int j_loc = warp_j * 32 + jt * 16 + rr * 8 + g;
            const int j_g = j0 + j_loc;
            int d = j_g - i_g;
            d = (d > 127 ? 127 : (d < -127 ? -127 : d)) + 127;
            const float* rB = g_Bv + (b * LQ + j_g) * HQ;
            const float* rT = g_T + d * HQ;
            float part[5] = {0.f, 0.f, 0.f, 0.f, 0.f};
            #pragma unroll
            for (int ht = 0; ht < 8; ++ht) {
                const int h = warp_h * 64 + ht * 8 + c2;
                float dv0 = acc[jt][ht][rr * 2 + 0];
                float dv1 = acc[jt][ht][rr * 2 + 1];
                float2 bv = *(const float2*)(rB + h);
                float2 tv = *(const float2*)(rT + h);
                float th0 = tanhfast(dv0 + sAi[h]     + bv.x + tv.x);
                float th1 = tanhfast(dv1 + sAi[h + 1] + bv.y + tv.y);
                #pragma unroll
                for (int cc = 0; cc < 5; ++cc) {
                    float2 wv = *(const float2*)&sWoT[cc][h];
                    part[cc] = fmaf(th0, wv.x, fmaf(th1, wv.y, part[cc]));
                }
            }
            #pragma unroll
            for (int cc = 0; cc < 5; ++cc) {
                part[cc] += __shfl_xor_sync(0xffffffffu, part[cc], 1);
                part[cc] += __shfl_xor_sync(0xffffffffu, part[cc], 2);
            }
            if ((lane & 3) == 0) {
                #pragma unroll
                for (int cc = 0; cc < 5; ++cc)
                    sPart[warp_h][cc][j_loc] = part[cc];
            }
        }
    }
    __syncthreads();

    const int mi = mask[b * LQ + i_g];
    for (int idx = t; idx < CQ * 128; idx += 512) {
        const int cc = idx >> 7, jl = idx & 127;
        const int j_g = j0 + jl;
        const int mj = mask[b * LQ + j_g];
        float v = sPart[0][cc][jl] + sPart[1][cc][jl]
                + sPart[2][cc][jl] + sPart[3][cc][jl] + Wo_b[cc];
        if (mi == 0 || mj == 0) v = -CUDART_INF_F;
        else if (i_g > j_g)     v -= 1e12f;
        out[((b * CQ + cc) * LQ + i_g) * LQ + j_g] = v;
    }
}

// ---------------------------------------------------------------------------
extern "C" void kernel_launch(void* const* d_in, const int* in_sizes, int n_in,
                              void* d_out, int out_size) {
    const float* hs   = nullptr;   // 131072
    const int*   mask = nullptr;   // 512
    const float* Wh_w = nullptr;   // 262144
    const float* Wh_b = nullptr;   // 256
    const float* Wo_w = nullptr;   // 1280
    const float* Wo_b = nullptr;   // 5
    for (int i = 0; i < n_in; ++i) {
        switch (in_sizes[i]) {
            case 131072: hs   = (const float*)d_in[i]; break;
            case 512:    mask = (const int*)  d_in[i]; break;
            case 262144: Wh_w = (const float*)d_in[i]; break;
            case 256:    Wh_b = (const float*)d_in[i]; break;
            case 1280:   Wo_w = (const float*)d_in[i]; break;
            case 5:      Wo_b = (const float*)d_in[i]; break;
        }
    }
    float* out = (float*)d_out;

    k_prep<<<192, 256>>>(hs, Wh_w, Wh_b);
    {
        dim3 grid(LQ / 128, LQ, BQ);     // (2, 256, 2) = 1024 blocks
        k_main<<<grid, 512>>>(hs, mask, Wo_w, Wo_b, out);
    }
}